// round 14
// baseline (speedup 1.0000x reference)
#include <cuda_runtime.h>
#include <cuda_bf16.h>
#include <math.h>
#include <stdint.h>

#define B_  64
#define D_  256
#define BM  128
#define KC  64
#define NCH 4
#define INV_TEMP 20.0f
#define MOM 0.2f
#define MAX_BLK 1600

// ---- dynamic smem layout (bytes) ----
// Xh [64][528]   @ 0       (33792)  row stride 528B -> conflict-free ldmatrix
// Xl [64][528]   @ 33792
// A  [hi|lo] 128x144 each  @ 67584  (36864), single buffer
#define XH_OFF   0
#define XL_OFF   33792
#define A_OFF    67584
#define A_PLANE  18432
#define SMEM_BYTES 104448

// scratch (no allocations allowed)
__device__ float g_xn[B_ * D_];                 // normalized inputs [b][d]
__device__ float g_tlogit[B_];
__device__ float g_psum[MAX_BLK * B_];          // per-tile exp-sums [tile][b]
__device__ unsigned int g_ctr;                  // finished-CTA counter (reset by prep)
__device__ __align__(16) uint32_t g_xh[8192];   // X bf16-hi, [64][128] bf16x2 words
__device__ __align__(16) uint32_t g_xl[8192];   // X bf16-lo

// ---------------- helpers ----------------
__device__ __forceinline__ uint32_t bf2(float hi, float lo) {
    uint32_t r;
    asm("cvt.rn.bf16x2.f32 %0, %1, %2;" : "=r"(r) : "f"(hi), "f"(lo));
    return r;
}
__device__ __forceinline__ void cp_async16(uint32_t dst, const void* src) {
    asm volatile("cp.async.ca.shared.global [%0], [%1], 16;" :: "r"(dst), "l"(src));
}
__device__ __forceinline__ void cp_commit() { asm volatile("cp.async.commit_group;"); }

__device__ __forceinline__ void ldm_x4(uint32_t addr, uint32_t r[4]) {
    asm volatile("ldmatrix.sync.aligned.m8n8.x4.shared.b16 {%0,%1,%2,%3}, [%4];"
                 : "=r"(r[0]), "=r"(r[1]), "=r"(r[2]), "=r"(r[3]) : "r"(addr));
}
__device__ __forceinline__ void mma_bf16(float c[4], const uint32_t a[4],
                                         const uint32_t b[2]) {
    asm volatile("mma.sync.aligned.m16n8k16.row.col.f32.bf16.bf16.f32 "
                 "{%0,%1,%2,%3}, {%4,%5,%6,%7}, {%8,%9}, {%0,%1,%2,%3};"
                 : "+f"(c[0]), "+f"(c[1]), "+f"(c[2]), "+f"(c[3])
                 : "r"(a[0]), "r"(a[1]), "r"(a[2]), "r"(a[3]),
                   "r"(b[0]), "r"(b[1]));
}

// ---------------------------------------------------------------------------
// Kernel 1 (fused prep): normalize inputs + bf16 hi/lo X planes + target logit
// Also resets the finished-CTA counter (graph-replay safe).
// ---------------------------------------------------------------------------
__global__ void prep_kernel(const float* __restrict__ inp,
                            const float* __restrict__ F,
                            const int* __restrict__ tgt) {
    int tid = threadIdx.x;
    int w = tid >> 5, lane = tid & 31;
    if (tid == 0) g_ctr = 0;

    // Phase A: normalize
    for (int b = w; b < B_; b += 8) {
        float v[8]; float ss = 0.f;
        #pragma unroll
        for (int t = 0; t < 8; t++) {
            v[t] = inp[b * D_ + lane + 32 * t];
            ss += v[t] * v[t];
        }
        #pragma unroll
        for (int off = 16; off; off >>= 1) ss += __shfl_xor_sync(0xffffffffu, ss, off);
        float inv = 1.0f / fmaxf(sqrtf(ss), 1e-12f);
        #pragma unroll
        for (int t = 0; t < 8; t++)
            g_xn[b * D_ + lane + 32 * t] = v[t] * inv;
    }
    __syncthreads();   // block-level visibility of g_xn

    // Phase B: bf16 hi/lo planes
    for (int p = tid; p < 8192; p += 256) {
        int b = p >> 7, pp = p & 127;
        float v0 = g_xn[b * D_ + 2 * pp];
        float v1 = g_xn[b * D_ + 2 * pp + 1];
        float h0 = __bfloat162float(__float2bfloat16_rn(v0));
        float h1 = __bfloat162float(__float2bfloat16_rn(v1));
        g_xh[p] = bf2(v1, v0);
        g_xl[p] = bf2(v1 - h1, v0 - h0);
    }

    // Phase C: logit at target
    for (int b = w; b < B_; b += 8) {
        long long t64 = (long long)tgt[b];
        float dot = 0.f;
        #pragma unroll
        for (int t = 0; t < 8; t++)
            dot += g_xn[b * D_ + lane + 32 * t] * F[t64 * (long long)D_ + lane + 32 * t];
        #pragma unroll
        for (int off = 16; off; off >>= 1) dot += __shfl_xor_sync(0xffffffffu, dot, off);
        if (lane == 0) g_tlogit[b] = dot * INV_TEMP;
    }
}

// ---------------------------------------------------------------------------
// Kernel 2 (main): bf16 split-GEMM via mma.sync + fused scatter-update of
// owned target rows + last-CTA deterministic reduction -> loss.
// ---------------------------------------------------------------------------
__global__ __launch_bounds__(256, 2) void main_kernel(const float* __restrict__ F,
                                                      const float* __restrict__ scores,
                                                      const int* __restrict__ tgt,
                                                      float* __restrict__ outF,
                                                      float* __restrict__ out,
                                                      int N) {
    extern __shared__ __align__(16) char smem[];
    const uint32_t sb = (uint32_t)__cvta_generic_to_shared(smem);

    const int tid = threadIdx.x;
    const int wid = tid >> 5, lane = tid & 31;
    const int wm = wid >> 1, wn = wid & 1;
    const int g = lane >> 2, t = lane & 3;
    const int row0 = blockIdx.x * BM;
    const int rows = min(BM, N - row0);
    const int nblk = gridDim.x;

    const int lr = tid >> 4;          // loader row base (0..15), +16*q
    const int lg = tid & 15;          // loader float4 col (0..15)

    // ---- X planes via cp.async ----
    #pragma unroll
    for (int q = 0; q < 16; q++) {
        int h = tid + 256 * q;               // 0..4095
        int plane = h >> 11, rem = h & 2047;
        int row = rem >> 5, c = rem & 31;
        const char* src = (plane ? (const char*)g_xl : (const char*)g_xh) + rem * 16;
        uint32_t dst = sb + (plane ? XL_OFF : XH_OFF) + row * 528 + c * 16;
        cp_async16(dst, src);
    }
    cp_commit();

    float acc[2][4][4];
    #pragma unroll
    for (int m = 0; m < 2; m++)
        #pragma unroll
        for (int n = 0; n < 4; n++)
            #pragma unroll
            for (int e = 0; e < 4; e++) acc[m][n][e] = 0.f;

    const uint32_t a_lane_off = (uint32_t)((wm * 32 + (lane & 15)) * 144 + (lane >> 4) * 16);
    const uint32_t b_lane_off = (uint32_t)((wn * 32 + (lane & 7) + ((lane >> 4) << 3)) * 528
                                           + ((lane >> 3) & 1) * 16);
    const uint32_t ah_buf = sb + A_OFF;

    // ---- prefetch chunk 0 into registers ----
    float4 v[8];
    #pragma unroll
    for (int q = 0; q < 8; q++) {
        int r = lr + 16 * q;
        v[q] = (r < rows)
             ? *reinterpret_cast<const float4*>(F + (size_t)(row0 + r) * D_ + lg * 4)
             : make_float4(0.f, 0.f, 0.f, 0.f);
    }

    for (int s = 0; s < NCH; s++) {
        // ---- convert chunk s + reload v[q] for chunk s+1 right after use ----
        #pragma unroll
        for (int q = 0; q < 8; q++) {
            int r = lr + 16 * q;
            float4 w = v[q];
            if (r < rows) {
                size_t off = (size_t)(row0 + r) * D_ + s * KC + lg * 4;
                outF[off + 0] = w.x;    // outF = out+1, 4B-aligned only
                outF[off + 1] = w.y;
                outF[off + 2] = w.z;
                outF[off + 3] = w.w;
            }
            float hx = __bfloat162float(__float2bfloat16_rn(w.x));
            float hy = __bfloat162float(__float2bfloat16_rn(w.y));
            float hz = __bfloat162float(__float2bfloat16_rn(w.z));
            float hw = __bfloat162float(__float2bfloat16_rn(w.w));
            uint32_t h0 = bf2(w.y, w.x), h1 = bf2(w.w, w.z);
            uint32_t l0 = bf2(w.y - hy, w.x - hx), l1 = bf2(w.w - hw, w.z - hz);
            uint32_t dsth = ah_buf + r * 144 + lg * 8;
            asm volatile("st.shared.v2.u32 [%0], {%1,%2};"
                         :: "r"(dsth), "r"(h0), "r"(h1) : "memory");
            asm volatile("st.shared.v2.u32 [%0], {%1,%2};"
                         :: "r"(dsth + A_PLANE), "r"(l0), "r"(l1) : "memory");
            // reload: consumed only after barrier + full MMA phase of chunk s
            if (s + 1 < NCH) {
                v[q] = (r < rows)
                     ? *reinterpret_cast<const float4*>(
                           F + (size_t)(row0 + r) * D_ + (s + 1) * KC + lg * 4)
                     : make_float4(0.f, 0.f, 0.f, 0.f);
            }
        }
        if (s == 0) asm volatile("cp.async.wait_group 0;");   // X resident
        __syncthreads();                                      // A ready

        // ---- MMA: 4 k16 chunks ----
        const uint32_t xh_b = sb + XH_OFF + b_lane_off + s * 128;
        #pragma unroll
        for (int kk = 0; kk < 4; kk++) {
            uint32_t aH0[4], aH1[4], aL0[4], aL1[4], bH[2][4], bL[2][4];
            uint32_t aoff = ah_buf + a_lane_off + kk * 32;
            ldm_x4(aoff, aH0);
            ldm_x4(aoff + 16 * 144, aH1);
            ldm_x4(aoff + A_PLANE, aL0);
            ldm_x4(aoff + A_PLANE + 16 * 144, aL1);
            uint32_t boff = xh_b + kk * 32;
            ldm_x4(boff, bH[0]);
            ldm_x4(boff + 16 * 528, bH[1]);
            ldm_x4(boff + XL_OFF, bL[0]);
            ldm_x4(boff + XL_OFF + 16 * 528, bL[1]);
            #pragma unroll
            for (int m = 0; m < 2; m++) {
                const uint32_t* ah = m ? aH1 : aH0;
                const uint32_t* al = m ? aL1 : aL0;
                #pragma unroll
                for (int n = 0; n < 4; n++) {
                    const uint32_t* bh = &bH[n >> 1][(n & 1) * 2];
                    const uint32_t* bl = &bL[n >> 1][(n & 1) * 2];
                    mma_bf16(acc[m][n], ah, bh);   // hi*hi
                    mma_bf16(acc[m][n], ah, bl);   // hi*lo
                    mma_bf16(acc[m][n], al, bh);   // lo*hi
                }
            }
        }
        if (s + 1 < NCH) __syncthreads();          // A consumed (skip on last)
    }

    // ---- epilogue: per-sample column sums of exp(20*dot) ----
    float cs0[4] = {0.f, 0.f, 0.f, 0.f}, cs1[4] = {0.f, 0.f, 0.f, 0.f};
    #pragma unroll
    for (int m = 0; m < 2; m++) {
        bool v0 = (row0 + wm * 32 + m * 16 + g) < N;
        bool v1 = (row0 + wm * 32 + m * 16 + g + 8) < N;
        #pragma unroll
        for (int n = 0; n < 4; n++) {
            float e0 = v0 ? __expf(INV_TEMP * acc[m][n][0]) : 0.f;
            float e1 = v0 ? __expf(INV_TEMP * acc[m][n][1]) : 0.f;
            float e2 = v1 ? __expf(INV_TEMP * acc[m][n][2]) : 0.f;
            float e3 = v1 ? __expf(INV_TEMP * acc[m][n][3]) : 0.f;
            cs0[n] += e0 + e2;
            cs1[n] += e1 + e3;
        }
    }
    #pragma unroll
    for (int off = 4; off <= 16; off <<= 1) {
        #pragma unroll
        for (int n = 0; n < 4; n++) {
            cs0[n] += __shfl_xor_sync(0xffffffffu, cs0[n], off);
            cs1[n] += __shfl_xor_sync(0xffffffffu, cs1[n], off);
        }
    }
    __syncthreads();                               // MMA smem reads done
    float* colsum = reinterpret_cast<float*>(smem + A_OFF);   // reuse A: [4][64]
    if (lane < 4) {
        #pragma unroll
        for (int n = 0; n < 4; n++) {
            colsum[wm * 64 + wn * 32 + 8 * n + 2 * t]     = cs0[n];
            colsum[wm * 64 + wn * 32 + 8 * n + 2 * t + 1] = cs1[n];
        }
    }
    __syncthreads();
    if (tid < 64) {
        float ssum = colsum[tid] + colsum[64 + tid] + colsum[128 + tid] + colsum[192 + tid];
        g_psum[blockIdx.x * B_ + tid] = ssum;
    }

    // ---- fused scatter: update target rows owned by this tile ----
    // Uniform control flow across the block (depends only on tgt/row0).
    for (int b = 0; b < B_; b++) {
        int tg = tgt[b];
        if (tg < row0 || tg >= row0 + BM) continue;
        bool dup = false;
        for (int b2 = b + 1; b2 < B_; b2++)
            if (tgt[b2] == tg) { dup = true; break; }
        if (dup) continue;                 // last duplicate wins
        float sc = scores[b];
        float u[4]; float ss = 0.f;
        if (tid < 64) {
            #pragma unroll
            for (int q = 0; q < 4; q++) {
                int d = tid + 64 * q;
                float oldv = F[(long long)tg * D_ + d];
                float xb = g_xn[b * D_ + d];
                u[q] = MOM * oldv + (1.0f - MOM) * sc * xb;
                ss += u[q] * u[q];
            }
            #pragma unroll
            for (int off = 16; off; off >>= 1)
                ss += __shfl_xor_sync(0xffffffffu, ss, off);
            if ((tid & 31) == 0) colsum[256 + (tid >> 5)] = ss;  // scratch
        }
        __syncthreads();
        if (tid < 64) {
            float tot = colsum[256] + colsum[257];
            float inv = 1.0f / fmaxf(sqrtf(tot), 1e-12f);
            #pragma unroll
            for (int q = 0; q < 4; q++)
                outF[(long long)tg * D_ + tid + 64 * q] = u[q] * inv;
        }
        __syncthreads();
    }

    // ---- last-CTA deterministic reduction -> loss ----
    __threadfence();
    __shared__ bool isLast;
    if (tid == 0)
        isLast = (atomicAdd(&g_ctr, 1u) == (unsigned)(nblk - 1));
    __syncthreads();
    if (isLast) {
        int b = tid & 63, sl = tid >> 6;   // 4 slices x 64 samples
        float s = 0.f;
        for (int i = sl; i < nblk; i += 4)
            s += __ldcg(&g_psum[i * B_ + b]);
        colsum[sl * 64 + b] = s;
        __syncthreads();
        if (tid < 64) {
            float S = colsum[tid] + colsum[64 + tid] + colsum[128 + tid] + colsum[192 + tid];
            colsum[256 + tid] = scores[tid] * (logf(S) - g_tlogit[tid]);
        }
        __syncthreads();
        if (tid == 0) {
            float accL = 0.f;
            #pragma unroll
            for (int i = 0; i < 64; i++) accL += colsum[256 + i];
            out[0] = accL;
        }
    }
}

// ---------------------------------------------------------------------------
extern "C" void kernel_launch(void* const* d_in, const int* in_sizes, int n_in,
                              void* d_out, int out_size) {
    const float* inputs   = (const float*)d_in[0];
    const float* scores   = (const float*)d_in[1];
    const float* features = (const float*)d_in[2];
    const int*   targets  = (const int*)d_in[3];
    int N = in_sizes[2] / D_;
    float* out = (float*)d_out;
    float* outF = out + 1;
    int nblk = (N + BM - 1) / BM;

    cudaFuncSetAttribute(main_kernel,
                         cudaFuncAttributeMaxDynamicSharedMemorySize, SMEM_BYTES);

    prep_kernel<<<1, 256>>>(inputs, features, targets);
    main_kernel<<<nblk, 256, SMEM_BYTES>>>(features, scores, targets, outF, out, N);
}

// round 15
// speedup vs baseline: 1.1893x; 1.1893x over previous
#include <cuda_runtime.h>
#include <cuda_bf16.h>
#include <math.h>
#include <stdint.h>

#define B_  64
#define D_  256
#define BM  128
#define KC  64
#define NCH 4
#define INV_TEMP 20.0f
#define MOM 0.2f
#define MAX_BLK 1600

// ---- dynamic smem layout (bytes) ----
// Xh [64][528]   @ 0       (33792)  row stride 528B -> conflict-free ldmatrix
// Xl [64][528]   @ 33792
// A  [hi|lo] 128x144 each  @ 67584  (36864), single buffer
#define XH_OFF   0
#define XL_OFF   33792
#define A_OFF    67584
#define A_PLANE  18432
#define SMEM_BYTES 104448

// scratch (no allocations allowed)
__device__ float g_xn[B_ * D_];                 // normalized inputs [b][d]
__device__ float g_tlogit[B_];
__device__ float g_psum[MAX_BLK * B_];          // per-tile exp-sums [tile][b]
__device__ unsigned int g_ctr;                  // finished-CTA counter (reset by prep)
__device__ __align__(16) uint32_t g_xh[8192];   // X bf16-hi, [64][128] bf16x2 words
__device__ __align__(16) uint32_t g_xl[8192];   // X bf16-lo

// ---------------- helpers ----------------
__device__ __forceinline__ uint32_t bf2(float hi, float lo) {
    uint32_t r;
    asm("cvt.rn.bf16x2.f32 %0, %1, %2;" : "=r"(r) : "f"(hi), "f"(lo));
    return r;
}
__device__ __forceinline__ void cp_async16(uint32_t dst, const void* src) {
    asm volatile("cp.async.ca.shared.global [%0], [%1], 16;" :: "r"(dst), "l"(src));
}
__device__ __forceinline__ void cp_commit() { asm volatile("cp.async.commit_group;"); }

__device__ __forceinline__ void ldm_x4(uint32_t addr, uint32_t r[4]) {
    asm volatile("ldmatrix.sync.aligned.m8n8.x4.shared.b16 {%0,%1,%2,%3}, [%4];"
                 : "=r"(r[0]), "=r"(r[1]), "=r"(r[2]), "=r"(r[3]) : "r"(addr));
}
__device__ __forceinline__ void mma_bf16(float c[4], const uint32_t a[4],
                                         const uint32_t b[2]) {
    asm volatile("mma.sync.aligned.m16n8k16.row.col.f32.bf16.bf16.f32 "
                 "{%0,%1,%2,%3}, {%4,%5,%6,%7}, {%8,%9}, {%0,%1,%2,%3};"
                 : "+f"(c[0]), "+f"(c[1]), "+f"(c[2]), "+f"(c[3])
                 : "r"(a[0]), "r"(a[1]), "r"(a[2]), "r"(a[3]),
                   "r"(b[0]), "r"(b[1]));
}

// ---------------------------------------------------------------------------
// Kernel 1 (fused prep): normalize inputs + bf16 hi/lo X planes + target logit
// Also resets the finished-CTA counter (graph-replay safe).
// ---------------------------------------------------------------------------
__global__ void prep_kernel(const float* __restrict__ inp,
                            const float* __restrict__ F,
                            const int* __restrict__ tgt) {
    int tid = threadIdx.x;
    int w = tid >> 5, lane = tid & 31;
    if (tid == 0) g_ctr = 0;

    // Phase A: normalize
    for (int b = w; b < B_; b += 8) {
        float v[8]; float ss = 0.f;
        #pragma unroll
        for (int t = 0; t < 8; t++) {
            v[t] = inp[b * D_ + lane + 32 * t];
            ss += v[t] * v[t];
        }
        #pragma unroll
        for (int off = 16; off; off >>= 1) ss += __shfl_xor_sync(0xffffffffu, ss, off);
        float inv = 1.0f / fmaxf(sqrtf(ss), 1e-12f);
        #pragma unroll
        for (int t = 0; t < 8; t++)
            g_xn[b * D_ + lane + 32 * t] = v[t] * inv;
    }
    __syncthreads();   // block-level visibility of g_xn

    // Phase B: bf16 hi/lo planes
    for (int p = tid; p < 8192; p += 256) {
        int b = p >> 7, pp = p & 127;
        float v0 = g_xn[b * D_ + 2 * pp];
        float v1 = g_xn[b * D_ + 2 * pp + 1];
        float h0 = __bfloat162float(__float2bfloat16_rn(v0));
        float h1 = __bfloat162float(__float2bfloat16_rn(v1));
        g_xh[p] = bf2(v1, v0);
        g_xl[p] = bf2(v1 - h1, v0 - h0);
    }

    // Phase C: logit at target
    for (int b = w; b < B_; b += 8) {
        long long t64 = (long long)tgt[b];
        float dot = 0.f;
        #pragma unroll
        for (int t = 0; t < 8; t++)
            dot += g_xn[b * D_ + lane + 32 * t] * F[t64 * (long long)D_ + lane + 32 * t];
        #pragma unroll
        for (int off = 16; off; off >>= 1) dot += __shfl_xor_sync(0xffffffffu, dot, off);
        if (lane == 0) g_tlogit[b] = dot * INV_TEMP;
    }
}

// ---------------------------------------------------------------------------
// Kernel 2 (main): bf16 split-GEMM via mma.sync + O(1) fused scatter check
// (smem-staged targets, block skip-flag) + last-CTA reduction -> loss.
// ---------------------------------------------------------------------------
__global__ __launch_bounds__(256, 2) void main_kernel(const float* __restrict__ F,
                                                      const float* __restrict__ scores,
                                                      const int* __restrict__ tgt,
                                                      float* __restrict__ outF,
                                                      float* __restrict__ out,
                                                      int N) {
    extern __shared__ __align__(16) char smem[];
    const uint32_t sb = (uint32_t)__cvta_generic_to_shared(smem);
    __shared__ int   s_tgt[B_];
    __shared__ float s_sc[B_];
    __shared__ int   s_own[B_];
    __shared__ int   s_has;
    __shared__ bool  isLast;

    const int tid = threadIdx.x;
    const int wid = tid >> 5, lane = tid & 31;
    const int wm = wid >> 1, wn = wid & 1;
    const int g = lane >> 2, t = lane & 3;
    const int row0 = blockIdx.x * BM;
    const int rows = min(BM, N - row0);
    const int nblk = gridDim.x;

    const int lr = tid >> 4;          // loader row base (0..15), +16*q
    const int lg = tid & 15;          // loader float4 col (0..15)

    // stage targets/scores once (coalesced)
    if (tid < B_) { s_tgt[tid] = tgt[tid]; s_sc[tid] = scores[tid]; }
    if (tid == 0) s_has = 0;

    // ---- X planes via cp.async ----
    #pragma unroll
    for (int q = 0; q < 16; q++) {
        int h = tid + 256 * q;               // 0..4095
        int plane = h >> 11, rem = h & 2047;
        int row = rem >> 5, c = rem & 31;
        const char* src = (plane ? (const char*)g_xl : (const char*)g_xh) + rem * 16;
        uint32_t dst = sb + (plane ? XL_OFF : XH_OFF) + row * 528 + c * 16;
        cp_async16(dst, src);
    }
    cp_commit();

    float acc[2][4][4];
    #pragma unroll
    for (int m = 0; m < 2; m++)
        #pragma unroll
        for (int n = 0; n < 4; n++)
            #pragma unroll
            for (int e = 0; e < 4; e++) acc[m][n][e] = 0.f;

    const uint32_t a_lane_off = (uint32_t)((wm * 32 + (lane & 15)) * 144 + (lane >> 4) * 16);
    const uint32_t b_lane_off = (uint32_t)((wn * 32 + (lane & 7) + ((lane >> 4) << 3)) * 528
                                           + ((lane >> 3) & 1) * 16);
    const uint32_t ah_buf = sb + A_OFF;

    // ---- prefetch chunk 0 into registers ----
    float4 v[8];
    #pragma unroll
    for (int q = 0; q < 8; q++) {
        int r = lr + 16 * q;
        v[q] = (r < rows)
             ? *reinterpret_cast<const float4*>(F + (size_t)(row0 + r) * D_ + lg * 4)
             : make_float4(0.f, 0.f, 0.f, 0.f);
    }

    for (int s = 0; s < NCH; s++) {
        // ---- convert chunk s + reload v[q] for chunk s+1 right after use ----
        #pragma unroll
        for (int q = 0; q < 8; q++) {
            int r = lr + 16 * q;
            float4 w = v[q];
            if (r < rows) {
                size_t off = (size_t)(row0 + r) * D_ + s * KC + lg * 4;
                outF[off + 0] = w.x;    // outF = out+1, 4B-aligned only
                outF[off + 1] = w.y;
                outF[off + 2] = w.z;
                outF[off + 3] = w.w;
            }
            float hx = __bfloat162float(__float2bfloat16_rn(w.x));
            float hy = __bfloat162float(__float2bfloat16_rn(w.y));
            float hz = __bfloat162float(__float2bfloat16_rn(w.z));
            float hw = __bfloat162float(__float2bfloat16_rn(w.w));
            uint32_t h0 = bf2(w.y, w.x), h1 = bf2(w.w, w.z);
            uint32_t l0 = bf2(w.y - hy, w.x - hx), l1 = bf2(w.w - hw, w.z - hz);
            uint32_t dsth = ah_buf + r * 144 + lg * 8;
            asm volatile("st.shared.v2.u32 [%0], {%1,%2};"
                         :: "r"(dsth), "r"(h0), "r"(h1) : "memory");
            asm volatile("st.shared.v2.u32 [%0], {%1,%2};"
                         :: "r"(dsth + A_PLANE), "r"(l0), "r"(l1) : "memory");
            // reload: consumed only after barrier + full MMA phase of chunk s
            if (s + 1 < NCH) {
                v[q] = (r < rows)
                     ? *reinterpret_cast<const float4*>(
                           F + (size_t)(row0 + r) * D_ + (s + 1) * KC + lg * 4)
                     : make_float4(0.f, 0.f, 0.f, 0.f);
            }
        }
        if (s == 0) asm volatile("cp.async.wait_group 0;");   // X resident
        __syncthreads();                                      // A ready

        // ---- MMA: 4 k16 chunks ----
        const uint32_t xh_b = sb + XH_OFF + b_lane_off + s * 128;
        #pragma unroll
        for (int kk = 0; kk < 4; kk++) {
            uint32_t aH0[4], aH1[4], aL0[4], aL1[4], bH[2][4], bL[2][4];
            uint32_t aoff = ah_buf + a_lane_off + kk * 32;
            ldm_x4(aoff, aH0);
            ldm_x4(aoff + 16 * 144, aH1);
            ldm_x4(aoff + A_PLANE, aL0);
            ldm_x4(aoff + A_PLANE + 16 * 144, aL1);
            uint32_t boff = xh_b + kk * 32;
            ldm_x4(boff, bH[0]);
            ldm_x4(boff + 16 * 528, bH[1]);
            ldm_x4(boff + XL_OFF, bL[0]);
            ldm_x4(boff + XL_OFF + 16 * 528, bL[1]);
            #pragma unroll
            for (int m = 0; m < 2; m++) {
                const uint32_t* ah = m ? aH1 : aH0;
                const uint32_t* al = m ? aL1 : aL0;
                #pragma unroll
                for (int n = 0; n < 4; n++) {
                    const uint32_t* bh = &bH[n >> 1][(n & 1) * 2];
                    const uint32_t* bl = &bL[n >> 1][(n & 1) * 2];
                    mma_bf16(acc[m][n], ah, bh);   // hi*hi
                    mma_bf16(acc[m][n], ah, bl);   // hi*lo
                    mma_bf16(acc[m][n], al, bh);   // lo*hi
                }
            }
        }
        if (s + 1 < NCH) __syncthreads();          // A consumed (skip on last)
    }

    // ---- epilogue: per-sample column sums of exp(20*dot) ----
    float cs0[4] = {0.f, 0.f, 0.f, 0.f}, cs1[4] = {0.f, 0.f, 0.f, 0.f};
    #pragma unroll
    for (int m = 0; m < 2; m++) {
        bool v0 = (row0 + wm * 32 + m * 16 + g) < N;
        bool v1 = (row0 + wm * 32 + m * 16 + g + 8) < N;
        #pragma unroll
        for (int n = 0; n < 4; n++) {
            float e0 = v0 ? __expf(INV_TEMP * acc[m][n][0]) : 0.f;
            float e1 = v0 ? __expf(INV_TEMP * acc[m][n][1]) : 0.f;
            float e2 = v1 ? __expf(INV_TEMP * acc[m][n][2]) : 0.f;
            float e3 = v1 ? __expf(INV_TEMP * acc[m][n][3]) : 0.f;
            cs0[n] += e0 + e2;
            cs1[n] += e1 + e3;
        }
    }
    #pragma unroll
    for (int off = 4; off <= 16; off <<= 1) {
        #pragma unroll
        for (int n = 0; n < 4; n++) {
            cs0[n] += __shfl_xor_sync(0xffffffffu, cs0[n], off);
            cs1[n] += __shfl_xor_sync(0xffffffffu, cs1[n], off);
        }
    }
    __syncthreads();                               // MMA smem reads done
    float* colsum = reinterpret_cast<float*>(smem + A_OFF);   // reuse A: [4][64]+
    if (lane < 4) {
        #pragma unroll
        for (int n = 0; n < 4; n++) {
            colsum[wm * 64 + wn * 32 + 8 * n + 2 * t]     = cs0[n];
            colsum[wm * 64 + wn * 32 + 8 * n + 2 * t + 1] = cs1[n];
        }
    }
    // own-flags computed in parallel with colsum stores (no extra barrier)
    if (tid < B_) {
        int tg = s_tgt[tid];
        int own = 0;
        if (tg >= row0 && tg < row0 + BM) {
            own = 1;
            for (int b2 = tid + 1; b2 < B_; b2++)
                if (s_tgt[b2] == tg) { own = 0; break; }   // last duplicate wins
            if (own) s_has = 1;                            // benign race, same value
        }
        s_own[tid] = own;
    }
    __syncthreads();
    if (tid < 64) {
        float ssum = colsum[tid] + colsum[64 + tid] + colsum[128 + tid] + colsum[192 + tid];
        g_psum[blockIdx.x * B_ + tid] = ssum;
    }

    // ---- fused scatter: only CTAs that own a target row do work ----
    if (s_has) {
        for (int b = 0; b < B_; b++) {
            if (!s_own[b]) continue;           // smem flag, uniform, cheap
            int tg = s_tgt[b];
            float sc = s_sc[b];
            float u[4]; float ss = 0.f;
            if (tid < 64) {
                #pragma unroll
                for (int q = 0; q < 4; q++) {
                    int d = tid + 64 * q;
                    float oldv = F[(long long)tg * D_ + d];
                    float xb = g_xn[b * D_ + d];
                    u[q] = MOM * oldv + (1.0f - MOM) * sc * xb;
                    ss += u[q] * u[q];
                }
                #pragma unroll
                for (int off = 16; off; off >>= 1)
                    ss += __shfl_xor_sync(0xffffffffu, ss, off);
                if ((tid & 31) == 0) colsum[256 + (tid >> 5)] = ss;
            }
            __syncthreads();
            if (tid < 64) {
                float tot = colsum[256] + colsum[257];
                float inv = 1.0f / fmaxf(sqrtf(tot), 1e-12f);
                #pragma unroll
                for (int q = 0; q < 4; q++)
                    outF[(long long)tg * D_ + tid + 64 * q] = u[q] * inv;
            }
            __syncthreads();
        }
    }

    // ---- last-CTA deterministic reduction -> loss ----
    __threadfence();
    if (tid == 0)
        isLast = (atomicAdd(&g_ctr, 1u) == (unsigned)(nblk - 1));
    __syncthreads();
    if (isLast) {
        int b = tid & 63, sl = tid >> 6;   // 4 slices x 64 samples
        float s = 0.f;
        for (int i = sl; i < nblk; i += 4)
            s += __ldcg(&g_psum[i * B_ + b]);
        colsum[sl * 64 + b] = s;
        __syncthreads();
        if (tid < 64) {
            float S = colsum[tid] + colsum[64 + tid] + colsum[128 + tid] + colsum[192 + tid];
            colsum[256 + tid] = s_sc[tid] * (logf(S) - g_tlogit[tid]);
        }
        __syncthreads();
        if (tid == 0) {
            float accL = 0.f;
            #pragma unroll
            for (int i = 0; i < 64; i++) accL += colsum[256 + i];
            out[0] = accL;
        }
    }
}

// ---------------------------------------------------------------------------
extern "C" void kernel_launch(void* const* d_in, const int* in_sizes, int n_in,
                              void* d_out, int out_size) {
    const float* inputs   = (const float*)d_in[0];
    const float* scores   = (const float*)d_in[1];
    const float* features = (const float*)d_in[2];
    const int*   targets  = (const int*)d_in[3];
    int N = in_sizes[2] / D_;
    float* out = (float*)d_out;
    float* outF = out + 1;
    int nblk = (N + BM - 1) / BM;

    cudaFuncSetAttribute(main_kernel,
                         cudaFuncAttributeMaxDynamicSharedMemorySize, SMEM_BYTES);

    prep_kernel<<<1, 256>>>(inputs, features, targets);
    main_kernel<<<nblk, 256, SMEM_BYTES>>>(features, scores, targets, outF, out, N);
}

// round 16
// speedup vs baseline: 1.4404x; 1.2111x over previous
#include <cuda_runtime.h>
#include <cuda_bf16.h>
#include <math.h>
#include <stdint.h>

#define B_  64
#define D_  256
#define BM  128
#define KC  64
#define NCH 4
#define INV_TEMP 20.0f
#define MOM 0.2f
#define MAX_BLK 1600

// ---- dynamic smem layout (bytes) ----
// Xh [64][528]   @ 0       (33792)  row stride 528B -> conflict-free ldmatrix
// Xl [64][528]   @ 33792
// A  [hi|lo] 128x144 each  @ 67584  (36864), single buffer
#define XH_OFF   0
#define XL_OFF   33792
#define A_OFF    67584
#define A_PLANE  18432
#define SMEM_BYTES 104448

// scratch (no allocations allowed)
__device__ float g_xn[B_ * D_];                 // normalized inputs [b][d]
__device__ float g_tlogit[B_];
__device__ float g_psum[B_ * MAX_BLK];          // per-tile exp-sums, [b][tile] (coalesced reduce)
__device__ float g_stot[B_];
__device__ unsigned int g_ctr;                  // finished-CTA counter (reset by prep)
__device__ __align__(16) uint32_t g_xh[8192];   // X bf16-hi, [64][128] bf16x2 words
__device__ __align__(16) uint32_t g_xl[8192];   // X bf16-lo

// ---------------- helpers ----------------
__device__ __forceinline__ uint32_t bf2(float hi, float lo) {
    uint32_t r;
    asm("cvt.rn.bf16x2.f32 %0, %1, %2;" : "=r"(r) : "f"(hi), "f"(lo));
    return r;
}
__device__ __forceinline__ void cp_async16(uint32_t dst, const void* src) {
    asm volatile("cp.async.ca.shared.global [%0], [%1], 16;" :: "r"(dst), "l"(src));
}
__device__ __forceinline__ void cp_commit() { asm volatile("cp.async.commit_group;"); }

__device__ __forceinline__ void ldm_x4(uint32_t addr, uint32_t r[4]) {
    asm volatile("ldmatrix.sync.aligned.m8n8.x4.shared.b16 {%0,%1,%2,%3}, [%4];"
                 : "=r"(r[0]), "=r"(r[1]), "=r"(r[2]), "=r"(r[3]) : "r"(addr));
}
__device__ __forceinline__ void mma_bf16(float c[4], const uint32_t a[4],
                                         const uint32_t b[2]) {
    asm volatile("mma.sync.aligned.m16n8k16.row.col.f32.bf16.bf16.f32 "
                 "{%0,%1,%2,%3}, {%4,%5,%6,%7}, {%8,%9}, {%0,%1,%2,%3};"
                 : "+f"(c[0]), "+f"(c[1]), "+f"(c[2]), "+f"(c[3])
                 : "r"(a[0]), "r"(a[1]), "r"(a[2]), "r"(a[3]),
                   "r"(b[0]), "r"(b[1]));
}

// ---------------------------------------------------------------------------
// Kernel 1 (prep, 64 CTAs x 32 thr): per-sample norm + bf16 planes + tlogit
// ---------------------------------------------------------------------------
__global__ void prep_kernel(const float* __restrict__ inp,
                            const float* __restrict__ F,
                            const int* __restrict__ tgt) {
    __shared__ float xr[D_];
    const int b = blockIdx.x;
    const int lane = threadIdx.x;              // 32 threads = 1 warp
    if (b == 0 && lane == 0) g_ctr = 0;

    float v[8]; float ss = 0.f;
    #pragma unroll
    for (int t = 0; t < 8; t++) {
        v[t] = inp[b * D_ + lane + 32 * t];
        ss += v[t] * v[t];
    }
    #pragma unroll
    for (int off = 16; off; off >>= 1) ss += __shfl_xor_sync(0xffffffffu, ss, off);
    float inv = 1.0f / fmaxf(sqrtf(ss), 1e-12f);
    #pragma unroll
    for (int t = 0; t < 8; t++) {
        float xv = v[t] * inv;
        xr[lane + 32 * t] = xv;
        g_xn[b * D_ + lane + 32 * t] = xv;
    }
    __syncwarp();

    // bf16 hi/lo planes: 128 words per row, 4 per thread
    #pragma unroll
    for (int w = 0; w < 4; w++) {
        int p = lane + 32 * w;
        float v0 = xr[2 * p], v1 = xr[2 * p + 1];
        float h0 = __bfloat162float(__float2bfloat16_rn(v0));
        float h1 = __bfloat162float(__float2bfloat16_rn(v1));
        g_xh[b * 128 + p] = bf2(v1, v0);
        g_xl[b * 128 + p] = bf2(v1 - h1, v0 - h0);
    }

    // logit at target
    long long t64 = (long long)tgt[b];
    float dot = 0.f;
    #pragma unroll
    for (int t = 0; t < 8; t++)
        dot += xr[lane + 32 * t] * F[t64 * (long long)D_ + lane + 32 * t];
    #pragma unroll
    for (int off = 16; off; off >>= 1) dot += __shfl_xor_sync(0xffffffffu, dot, off);
    if (lane == 0) g_tlogit[b] = dot * INV_TEMP;
}

// ---------------------------------------------------------------------------
// Kernel 2 (main): bf16 split-GEMM via mma.sync + fused scatter (O(1) check).
// No threadfence / in-kernel loss (that cost +23us in R15).
// ---------------------------------------------------------------------------
__global__ __launch_bounds__(256, 2) void main_kernel(const float* __restrict__ F,
                                                      const float* __restrict__ scores,
                                                      const int* __restrict__ tgt,
                                                      float* __restrict__ outF,
                                                      int N) {
    extern __shared__ __align__(16) char smem[];
    const uint32_t sb = (uint32_t)__cvta_generic_to_shared(smem);
    __shared__ int   s_tgt[B_];
    __shared__ float s_sc[B_];
    __shared__ int   s_own[B_];
    __shared__ int   s_has;

    const int tid = threadIdx.x;
    const int wid = tid >> 5, lane = tid & 31;
    const int wm = wid >> 1, wn = wid & 1;
    const int g = lane >> 2, t = lane & 3;
    const int row0 = blockIdx.x * BM;
    const int rows = min(BM, N - row0);

    const int lr = tid >> 4;          // loader row base (0..15), +16*q
    const int lg = tid & 15;          // loader float4 col (0..15)

    // stage targets/scores once (coalesced)
    if (tid < B_) { s_tgt[tid] = tgt[tid]; s_sc[tid] = scores[tid]; }
    if (tid == 0) s_has = 0;

    // ---- X planes via cp.async ----
    #pragma unroll
    for (int q = 0; q < 16; q++) {
        int h = tid + 256 * q;               // 0..4095
        int plane = h >> 11, rem = h & 2047;
        int row = rem >> 5, c = rem & 31;
        const char* src = (plane ? (const char*)g_xl : (const char*)g_xh) + rem * 16;
        uint32_t dst = sb + (plane ? XL_OFF : XH_OFF) + row * 528 + c * 16;
        cp_async16(dst, src);
    }
    cp_commit();

    float acc[2][4][4];
    #pragma unroll
    for (int m = 0; m < 2; m++)
        #pragma unroll
        for (int n = 0; n < 4; n++)
            #pragma unroll
            for (int e = 0; e < 4; e++) acc[m][n][e] = 0.f;

    const uint32_t a_lane_off = (uint32_t)((wm * 32 + (lane & 15)) * 144 + (lane >> 4) * 16);
    const uint32_t b_lane_off = (uint32_t)((wn * 32 + (lane & 7) + ((lane >> 4) << 3)) * 528
                                           + ((lane >> 3) & 1) * 16);
    const uint32_t ah_buf = sb + A_OFF;

    // ---- prefetch chunk 0 into registers ----
    float4 v[8];
    #pragma unroll
    for (int q = 0; q < 8; q++) {
        int r = lr + 16 * q;
        v[q] = (r < rows)
             ? *reinterpret_cast<const float4*>(F + (size_t)(row0 + r) * D_ + lg * 4)
             : make_float4(0.f, 0.f, 0.f, 0.f);
    }

    for (int s = 0; s < NCH; s++) {
        // ---- convert chunk s + reload v[q] for chunk s+1 right after use ----
        #pragma unroll
        for (int q = 0; q < 8; q++) {
            int r = lr + 16 * q;
            float4 w = v[q];
            if (r < rows) {
                size_t off = (size_t)(row0 + r) * D_ + s * KC + lg * 4;
                outF[off + 0] = w.x;    // outF = out+1, 4B-aligned only
                outF[off + 1] = w.y;
                outF[off + 2] = w.z;
                outF[off + 3] = w.w;
            }
            float hx = __bfloat162float(__float2bfloat16_rn(w.x));
            float hy = __bfloat162float(__float2bfloat16_rn(w.y));
            float hz = __bfloat162float(__float2bfloat16_rn(w.z));
            float hw = __bfloat162float(__float2bfloat16_rn(w.w));
            uint32_t h0 = bf2(w.y, w.x), h1 = bf2(w.w, w.z);
            uint32_t l0 = bf2(w.y - hy, w.x - hx), l1 = bf2(w.w - hw, w.z - hz);
            uint32_t dsth = ah_buf + r * 144 + lg * 8;
            asm volatile("st.shared.v2.u32 [%0], {%1,%2};"
                         :: "r"(dsth), "r"(h0), "r"(h1) : "memory");
            asm volatile("st.shared.v2.u32 [%0], {%1,%2};"
                         :: "r"(dsth + A_PLANE), "r"(l0), "r"(l1) : "memory");
            // reload: consumed only after barrier + full MMA phase of chunk s
            if (s + 1 < NCH) {
                v[q] = (r < rows)
                     ? *reinterpret_cast<const float4*>(
                           F + (size_t)(row0 + r) * D_ + (s + 1) * KC + lg * 4)
                     : make_float4(0.f, 0.f, 0.f, 0.f);
            }
        }
        if (s == 0) asm volatile("cp.async.wait_group 0;");   // X resident
        __syncthreads();                                      // A ready

        // ---- MMA: 4 k16 chunks ----
        const uint32_t xh_b = sb + XH_OFF + b_lane_off + s * 128;
        #pragma unroll
        for (int kk = 0; kk < 4; kk++) {
            uint32_t aH0[4], aH1[4], aL0[4], aL1[4], bH[2][4], bL[2][4];
            uint32_t aoff = ah_buf + a_lane_off + kk * 32;
            ldm_x4(aoff, aH0);
            ldm_x4(aoff + 16 * 144, aH1);
            ldm_x4(aoff + A_PLANE, aL0);
            ldm_x4(aoff + A_PLANE + 16 * 144, aL1);
            uint32_t boff = xh_b + kk * 32;
            ldm_x4(boff, bH[0]);
            ldm_x4(boff + 16 * 528, bH[1]);
            ldm_x4(boff + XL_OFF, bL[0]);
            ldm_x4(boff + XL_OFF + 16 * 528, bL[1]);
            #pragma unroll
            for (int m = 0; m < 2; m++) {
                const uint32_t* ah = m ? aH1 : aH0;
                const uint32_t* al = m ? aL1 : aL0;
                #pragma unroll
                for (int n = 0; n < 4; n++) {
                    const uint32_t* bh = &bH[n >> 1][(n & 1) * 2];
                    const uint32_t* bl = &bL[n >> 1][(n & 1) * 2];
                    mma_bf16(acc[m][n], ah, bh);   // hi*hi
                    mma_bf16(acc[m][n], ah, bl);   // hi*lo
                    mma_bf16(acc[m][n], al, bh);   // lo*hi
                }
            }
        }
        if (s + 1 < NCH) __syncthreads();          // A consumed (skip on last)
    }

    // ---- epilogue: per-sample column sums of exp(20*dot) ----
    float cs0[4] = {0.f, 0.f, 0.f, 0.f}, cs1[4] = {0.f, 0.f, 0.f, 0.f};
    #pragma unroll
    for (int m = 0; m < 2; m++) {
        bool v0 = (row0 + wm * 32 + m * 16 + g) < N;
        bool v1 = (row0 + wm * 32 + m * 16 + g + 8) < N;
        #pragma unroll
        for (int n = 0; n < 4; n++) {
            float e0 = v0 ? __expf(INV_TEMP * acc[m][n][0]) : 0.f;
            float e1 = v0 ? __expf(INV_TEMP * acc[m][n][1]) : 0.f;
            float e2 = v1 ? __expf(INV_TEMP * acc[m][n][2]) : 0.f;
            float e3 = v1 ? __expf(INV_TEMP * acc[m][n][3]) : 0.f;
            cs0[n] += e0 + e2;
            cs1[n] += e1 + e3;
        }
    }
    #pragma unroll
    for (int off = 4; off <= 16; off <<= 1) {
        #pragma unroll
        for (int n = 0; n < 4; n++) {
            cs0[n] += __shfl_xor_sync(0xffffffffu, cs0[n], off);
            cs1[n] += __shfl_xor_sync(0xffffffffu, cs1[n], off);
        }
    }
    __syncthreads();                               // MMA smem reads done
    float* colsum = reinterpret_cast<float*>(smem + A_OFF);   // reuse A: [4][64]+
    if (lane < 4) {
        #pragma unroll
        for (int n = 0; n < 4; n++) {
            colsum[wm * 64 + wn * 32 + 8 * n + 2 * t]     = cs0[n];
            colsum[wm * 64 + wn * 32 + 8 * n + 2 * t + 1] = cs1[n];
        }
    }
    // own-flags in parallel with colsum stores
    if (tid < B_) {
        int tg = s_tgt[tid];
        int own = 0;
        if (tg >= row0 && tg < row0 + BM) {
            own = 1;
            for (int b2 = tid + 1; b2 < B_; b2++)
                if (s_tgt[b2] == tg) { own = 0; break; }   // last duplicate wins
            if (own) s_has = 1;                            // benign race, same value
        }
        s_own[tid] = own;
    }
    __syncthreads();
    if (tid < 64) {
        float ssum = colsum[tid] + colsum[64 + tid] + colsum[128 + tid] + colsum[192 + tid];
        g_psum[tid * MAX_BLK + blockIdx.x] = ssum;   // [b][tile] for coalesced reduce
    }

    // ---- fused scatter: only CTAs that own a target row do work ----
    if (s_has) {
        for (int b = 0; b < B_; b++) {
            if (!s_own[b]) continue;           // smem flag, uniform, cheap
            int tg = s_tgt[b];
            float sc = s_sc[b];
            float u[4]; float ss = 0.f;
            if (tid < 64) {
                #pragma unroll
                for (int q = 0; q < 4; q++) {
                    int d = tid + 64 * q;
                    float oldv = F[(long long)tg * D_ + d];
                    float xb = g_xn[b * D_ + d];
                    u[q] = MOM * oldv + (1.0f - MOM) * sc * xb;
                    ss += u[q] * u[q];
                }
                #pragma unroll
                for (int off = 16; off; off >>= 1)
                    ss += __shfl_xor_sync(0xffffffffu, ss, off);
                if ((tid & 31) == 0) colsum[256 + (tid >> 5)] = ss;
            }
            __syncthreads();
            if (tid < 64) {
                float tot = colsum[256] + colsum[257];
                float inv = 1.0f / fmaxf(sqrtf(tot), 1e-12f);
                #pragma unroll
                for (int q = 0; q < 4; q++)
                    outF[(long long)tg * D_ + tid + 64 * q] = u[q] * inv;
            }
            __syncthreads();
        }
    }
}

// ---------------------------------------------------------------------------
// Kernel 3 (sumloss, 64 CTAs x 256 thr): coalesced per-sample sum, last CTA
// computes loss (threadfence trivial here: 1 small store in flight per CTA).
// ---------------------------------------------------------------------------
__global__ void sumloss_kernel(const float* __restrict__ scores,
                               float* __restrict__ out, int nblk) {
    __shared__ float sh[8];
    __shared__ bool isLast;
    const int b = blockIdx.x;
    const int tid = threadIdx.x;
    float s = 0.f;
    const float* ps = &g_psum[b * MAX_BLK];
    for (int i = tid; i < nblk; i += 256)
        s += ps[i];
    #pragma unroll
    for (int off = 16; off; off >>= 1) s += __shfl_xor_sync(0xffffffffu, s, off);
    if ((tid & 31) == 0) sh[tid >> 5] = s;
    __syncthreads();
    if (tid == 0) {
        float S = 0.f;
        #pragma unroll
        for (int q = 0; q < 8; q++) S += sh[q];
        g_stot[b] = S;
        __threadfence();
        isLast = (atomicAdd(&g_ctr, 1u) == (unsigned)(B_ - 1));
    }
    __syncthreads();
    if (isLast && tid < 64) {
        float lv = scores[tid] * (logf(__ldcg(&g_stot[tid])) - g_tlogit[tid]);
        #pragma unroll
        for (int off = 16; off; off >>= 1) lv += __shfl_xor_sync(0xffffffffu, lv, off);
        if ((tid & 31) == 0) sh[tid >> 5] = lv;
        __syncwarp();
        if (tid == 0) {
            // wait for warp1's sh[1] via bar
        }
    }
    __syncthreads();
    if (isLast && tid == 0) out[0] = sh[0] + sh[1];
}

// ---------------------------------------------------------------------------
extern "C" void kernel_launch(void* const* d_in, const int* in_sizes, int n_in,
                              void* d_out, int out_size) {
    const float* inputs   = (const float*)d_in[0];
    const float* scores   = (const float*)d_in[1];
    const float* features = (const float*)d_in[2];
    const int*   targets  = (const int*)d_in[3];
    int N = in_sizes[2] / D_;
    float* out = (float*)d_out;
    float* outF = out + 1;
    int nblk = (N + BM - 1) / BM;

    cudaFuncSetAttribute(main_kernel,
                         cudaFuncAttributeMaxDynamicSharedMemorySize, SMEM_BYTES);

    prep_kernel<<<B_, 32>>>(inputs, features, targets);
    main_kernel<<<nblk, 256, SMEM_BYTES>>>(features, scores, targets, outF, N);
    sumloss_kernel<<<B_, 256>>>(scores, out, nblk);
}

// round 17
// speedup vs baseline: 1.4864x; 1.0319x over previous
#include <cuda_runtime.h>
#include <cuda_bf16.h>
#include <math.h>
#include <stdint.h>

#define B_  64
#define D_  256
#define BM  128
#define KC  64
#define NCH 4
#define INV_TEMP 20.0f
#define MOM 0.2f
#define MAX_BLK 1600

// ---- dynamic smem layout (bytes) ----
// Xh [64][528]   @ 0       (33792)  row stride 528B -> conflict-free ldmatrix
// Xl [64][528]   @ 33792
// A  [hi|lo] 128x144 each  @ 67584  (36864), single buffer
#define XH_OFF   0
#define XL_OFF   33792
#define A_OFF    67584
#define A_PLANE  18432
#define SMEM_BYTES 104448

// scratch (no allocations allowed)
__device__ float g_xn[B_ * D_];                 // normalized inputs [b][d]
__device__ float g_tlogit[B_];
__device__ float g_psum[B_ * MAX_BLK];          // per-tile exp-sums, [b][tile]
__device__ float g_stot[B_];
__device__ unsigned int g_ctr;                  // finished-CTA counter (reset by prep)
__device__ __align__(16) uint32_t g_xh[8192];   // X bf16-hi, [64][128] bf16x2 words
__device__ __align__(16) uint32_t g_xl[8192];   // X bf16-lo

// ---------------- helpers ----------------
__device__ __forceinline__ uint32_t bf2(float hi, float lo) {
    uint32_t r;
    asm("cvt.rn.bf16x2.f32 %0, %1, %2;" : "=r"(r) : "f"(hi), "f"(lo));
    return r;
}
__device__ __forceinline__ void cp_async16(uint32_t dst, const void* src) {
    asm volatile("cp.async.ca.shared.global [%0], [%1], 16;" :: "r"(dst), "l"(src));
}
__device__ __forceinline__ void cp_commit() { asm volatile("cp.async.commit_group;"); }

__device__ __forceinline__ void ldm_x4(uint32_t addr, uint32_t r[4]) {
    asm volatile("ldmatrix.sync.aligned.m8n8.x4.shared.b16 {%0,%1,%2,%3}, [%4];"
                 : "=r"(r[0]), "=r"(r[1]), "=r"(r[2]), "=r"(r[3]) : "r"(addr));
}
__device__ __forceinline__ void mma_bf16(float c[4], const uint32_t a[4],
                                         const uint32_t b[2]) {
    asm volatile("mma.sync.aligned.m16n8k16.row.col.f32.bf16.bf16.f32 "
                 "{%0,%1,%2,%3}, {%4,%5,%6,%7}, {%8,%9}, {%0,%1,%2,%3};"
                 : "+f"(c[0]), "+f"(c[1]), "+f"(c[2]), "+f"(c[3])
                 : "r"(a[0]), "r"(a[1]), "r"(a[2]), "r"(a[3]),
                   "r"(b[0]), "r"(b[1]));
}

// ---------------------------------------------------------------------------
// Kernel 1 (prep, 64 CTAs x 32 thr): per-sample norm + bf16 planes + tlogit
// ---------------------------------------------------------------------------
__global__ void prep_kernel(const float* __restrict__ inp,
                            const float* __restrict__ F,
                            const int* __restrict__ tgt) {
    __shared__ float xr[D_];
    const int b = blockIdx.x;
    const int lane = threadIdx.x;              // 32 threads = 1 warp
    if (b == 0 && lane == 0) g_ctr = 0;

    float v[8]; float ss = 0.f;
    #pragma unroll
    for (int t = 0; t < 8; t++) {
        v[t] = inp[b * D_ + lane + 32 * t];
        ss += v[t] * v[t];
    }
    #pragma unroll
    for (int off = 16; off; off >>= 1) ss += __shfl_xor_sync(0xffffffffu, ss, off);
    float inv = 1.0f / fmaxf(sqrtf(ss), 1e-12f);
    #pragma unroll
    for (int t = 0; t < 8; t++) {
        float xv = v[t] * inv;
        xr[lane + 32 * t] = xv;
        g_xn[b * D_ + lane + 32 * t] = xv;
    }
    __syncwarp();

    // bf16 hi/lo planes: 128 words per row, 4 per thread
    #pragma unroll
    for (int w = 0; w < 4; w++) {
        int p = lane + 32 * w;
        float v0 = xr[2 * p], v1 = xr[2 * p + 1];
        float h0 = __bfloat162float(__float2bfloat16_rn(v0));
        float h1 = __bfloat162float(__float2bfloat16_rn(v1));
        g_xh[b * 128 + p] = bf2(v1, v0);
        g_xl[b * 128 + p] = bf2(v1 - h1, v0 - h0);
    }

    // logit at target
    long long t64 = (long long)tgt[b];
    float dot = 0.f;
    #pragma unroll
    for (int t = 0; t < 8; t++)
        dot += xr[lane + 32 * t] * F[t64 * (long long)D_ + lane + 32 * t];
    #pragma unroll
    for (int off = 16; off; off >>= 1) dot += __shfl_xor_sync(0xffffffffu, dot, off);
    if (lane == 0) g_tlogit[b] = dot * INV_TEMP;
}

// ---------------------------------------------------------------------------
// Kernel 2 (main): bf16 split-GEMM via mma.sync, warp-pair pipelined:
// A is partitioned by wm, so convert/MMA sync is pair-scoped (bar.sync id,64)
// -> pairs free-run and convert overlaps MMA within the CTA.
// ---------------------------------------------------------------------------
__global__ __launch_bounds__(256, 2) void main_kernel(const float* __restrict__ F,
                                                      const float* __restrict__ scores,
                                                      const int* __restrict__ tgt,
                                                      float* __restrict__ outF,
                                                      int N) {
    extern __shared__ __align__(16) char smem[];
    const uint32_t sb = (uint32_t)__cvta_generic_to_shared(smem);
    __shared__ int   s_tgt[B_];
    __shared__ float s_sc[B_];
    __shared__ int   s_own[B_];
    __shared__ int   s_has;

    const int tid = threadIdx.x;
    const int wid = tid >> 5, lane = tid & 31;
    const int wm = wid >> 1, wn = wid & 1;
    const int g = lane >> 2, t = lane & 3;
    const int row0 = blockIdx.x * BM;
    const int rows = min(BM, N - row0);

    // pair-local loader geometry: warp converts its pair's 16 rows
    const int rbase = wm * 32 + wn * 16 + (lane >> 4);   // + 2*q
    const int cq = lane & 15;                            // float4 col

    // stage targets/scores once (coalesced)
    if (tid < B_) { s_tgt[tid] = tgt[tid]; s_sc[tid] = scores[tid]; }
    if (tid == 0) s_has = 0;

    // ---- X planes via cp.async (block-cooperative) ----
    #pragma unroll
    for (int q = 0; q < 16; q++) {
        int h = tid + 256 * q;               // 0..4095
        int plane = h >> 11, rem = h & 2047;
        int row = rem >> 5, c = rem & 31;
        const char* src = (plane ? (const char*)g_xl : (const char*)g_xh) + rem * 16;
        uint32_t dst = sb + (plane ? XL_OFF : XH_OFF) + row * 528 + c * 16;
        cp_async16(dst, src);
    }
    cp_commit();

    float acc[2][4][4];
    #pragma unroll
    for (int m = 0; m < 2; m++)
        #pragma unroll
        for (int n = 0; n < 4; n++)
            #pragma unroll
            for (int e = 0; e < 4; e++) acc[m][n][e] = 0.f;

    const uint32_t a_lane_off = (uint32_t)((wm * 32 + (lane & 15)) * 144 + (lane >> 4) * 16);
    const uint32_t b_lane_off = (uint32_t)((wn * 32 + (lane & 7) + ((lane >> 4) << 3)) * 528
                                           + ((lane >> 3) & 1) * 16);
    const uint32_t ah_buf = sb + A_OFF;

    // ---- prefetch chunk 0 into registers (warp's own 16 rows) ----
    float4 v[8];
    #pragma unroll
    for (int q = 0; q < 8; q++) {
        int r = rbase + 2 * q;
        v[q] = (r < rows)
             ? *reinterpret_cast<const float4*>(F + (size_t)(row0 + r) * D_ + cq * 4)
             : make_float4(0.f, 0.f, 0.f, 0.f);
    }

    for (int s = 0; s < NCH; s++) {
        // ---- convert chunk s (own rows) + reload v[q] for chunk s+1 ----
        #pragma unroll
        for (int q = 0; q < 8; q++) {
            int r = rbase + 2 * q;
            float4 w = v[q];
            if (r < rows) {
                size_t off = (size_t)(row0 + r) * D_ + s * KC + cq * 4;
                outF[off + 0] = w.x;    // outF = out+1, 4B-aligned only
                outF[off + 1] = w.y;
                outF[off + 2] = w.z;
                outF[off + 3] = w.w;
            }
            float hx = __bfloat162float(__float2bfloat16_rn(w.x));
            float hy = __bfloat162float(__float2bfloat16_rn(w.y));
            float hz = __bfloat162float(__float2bfloat16_rn(w.z));
            float hw = __bfloat162float(__float2bfloat16_rn(w.w));
            uint32_t h0 = bf2(w.y, w.x), h1 = bf2(w.w, w.z);
            uint32_t l0 = bf2(w.y - hy, w.x - hx), l1 = bf2(w.w - hw, w.z - hz);
            uint32_t dsth = ah_buf + r * 144 + cq * 8;
            asm volatile("st.shared.v2.u32 [%0], {%1,%2};"
                         :: "r"(dsth), "r"(h0), "r"(h1) : "memory");
            asm volatile("st.shared.v2.u32 [%0], {%1,%2};"
                         :: "r"(dsth + A_PLANE), "r"(l0), "r"(l1) : "memory");
            // reload: consumed only after pair-bar + full MMA phase of chunk s
            if (s + 1 < NCH) {
                v[q] = (r < rows)
                     ? *reinterpret_cast<const float4*>(
                           F + (size_t)(row0 + r) * D_ + (s + 1) * KC + cq * 4)
                     : make_float4(0.f, 0.f, 0.f, 0.f);
            }
        }
        if (s == 0) {
            asm volatile("cp.async.wait_group 0;");   // X resident
            __syncthreads();                           // X visible to all + A(0) ready
        } else {
            asm volatile("bar.sync %0, 64;" :: "r"(wm + 1) : "memory");  // A ready (pair)
        }

        // ---- MMA: 4 k16 chunks ----
        const uint32_t xh_b = sb + XH_OFF + b_lane_off + s * 128;
        #pragma unroll
        for (int kk = 0; kk < 4; kk++) {
            uint32_t aH0[4], aH1[4], aL0[4], aL1[4], bH[2][4], bL[2][4];
            uint32_t aoff = ah_buf + a_lane_off + kk * 32;
            ldm_x4(aoff, aH0);
            ldm_x4(aoff + 16 * 144, aH1);
            ldm_x4(aoff + A_PLANE, aL0);
            ldm_x4(aoff + A_PLANE + 16 * 144, aL1);
            uint32_t boff = xh_b + kk * 32;
            ldm_x4(boff, bH[0]);
            ldm_x4(boff + 16 * 528, bH[1]);
            ldm_x4(boff + XL_OFF, bL[0]);
            ldm_x4(boff + XL_OFF + 16 * 528, bL[1]);
            #pragma unroll
            for (int m = 0; m < 2; m++) {
                const uint32_t* ah = m ? aH1 : aH0;
                const uint32_t* al = m ? aL1 : aL0;
                #pragma unroll
                for (int n = 0; n < 4; n++) {
                    const uint32_t* bh = &bH[n >> 1][(n & 1) * 2];
                    const uint32_t* bl = &bL[n >> 1][(n & 1) * 2];
                    mma_bf16(acc[m][n], ah, bh);   // hi*hi
                    mma_bf16(acc[m][n], ah, bl);   // hi*lo
                    mma_bf16(acc[m][n], al, bh);   // lo*hi
                }
            }
        }
        if (s + 1 < NCH)   // A consumed by pair -> next convert may overwrite
            asm volatile("bar.sync %0, 64;" :: "r"(wm + 1) : "memory");
    }

    // ---- epilogue: per-sample column sums of exp(20*dot) ----
    float cs0[4] = {0.f, 0.f, 0.f, 0.f}, cs1[4] = {0.f, 0.f, 0.f, 0.f};
    #pragma unroll
    for (int m = 0; m < 2; m++) {
        bool v0 = (row0 + wm * 32 + m * 16 + g) < N;
        bool v1 = (row0 + wm * 32 + m * 16 + g + 8) < N;
        #pragma unroll
        for (int n = 0; n < 4; n++) {
            float e0 = v0 ? __expf(INV_TEMP * acc[m][n][0]) : 0.f;
            float e1 = v0 ? __expf(INV_TEMP * acc[m][n][1]) : 0.f;
            float e2 = v1 ? __expf(INV_TEMP * acc[m][n][2]) : 0.f;
            float e3 = v1 ? __expf(INV_TEMP * acc[m][n][3]) : 0.f;
            cs0[n] += e0 + e2;
            cs1[n] += e1 + e3;
        }
    }
    #pragma unroll
    for (int off = 4; off <= 16; off <<= 1) {
        #pragma unroll
        for (int n = 0; n < 4; n++) {
            cs0[n] += __shfl_xor_sync(0xffffffffu, cs0[n], off);
            cs1[n] += __shfl_xor_sync(0xffffffffu, cs1[n], off);
        }
    }
    __syncthreads();                               // all MMA smem reads done (block)
    float* colsum = reinterpret_cast<float*>(smem + A_OFF);   // reuse A: [4][64]+
    if (lane < 4) {
        #pragma unroll
        for (int n = 0; n < 4; n++) {
            colsum[wm * 64 + wn * 32 + 8 * n + 2 * t]     = cs0[n];
            colsum[wm * 64 + wn * 32 + 8 * n + 2 * t + 1] = cs1[n];
        }
    }
    // own-flags in parallel with colsum stores
    if (tid < B_) {
        int tg = s_tgt[tid];
        int own = 0;
        if (tg >= row0 && tg < row0 + BM) {
            own = 1;
            for (int b2 = tid + 1; b2 < B_; b2++)
                if (s_tgt[b2] == tg) { own = 0; break; }   // last duplicate wins
            if (own) s_has = 1;                            // benign race, same value
        }
        s_own[tid] = own;
    }
    __syncthreads();
    if (tid < 64) {
        float ssum = colsum[tid] + colsum[64 + tid] + colsum[128 + tid] + colsum[192 + tid];
        g_psum[tid * MAX_BLK + blockIdx.x] = ssum;   // [b][tile] for coalesced reduce
    }

    // ---- fused scatter: only CTAs that own a target row do work ----
    if (s_has) {
        for (int b = 0; b < B_; b++) {
            if (!s_own[b]) continue;           // smem flag, uniform, cheap
            int tg = s_tgt[b];
            float sc = s_sc[b];
            float u[4]; float ss = 0.f;
            if (tid < 64) {
                #pragma unroll
                for (int q = 0; q < 4; q++) {
                    int d = tid + 64 * q;
                    float oldv = F[(long long)tg * D_ + d];
                    float xb = g_xn[b * D_ + d];
                    u[q] = MOM * oldv + (1.0f - MOM) * sc * xb;
                    ss += u[q] * u[q];
                }
                #pragma unroll
                for (int off = 16; off; off >>= 1)
                    ss += __shfl_xor_sync(0xffffffffu, ss, off);
                if ((tid & 31) == 0) colsum[256 + (tid >> 5)] = ss;
            }
            __syncthreads();
            if (tid < 64) {
                float tot = colsum[256] + colsum[257];
                float inv = 1.0f / fmaxf(sqrtf(tot), 1e-12f);
                #pragma unroll
                for (int q = 0; q < 4; q++)
                    outF[(long long)tg * D_ + tid + 64 * q] = u[q] * inv;
            }
            __syncthreads();
        }
    }
}

// ---------------------------------------------------------------------------
// Kernel 3 (sumloss, 64 CTAs x 256 thr): coalesced per-sample sum, last CTA
// computes loss (threadfence trivial here: 1 small store in flight per CTA).
// ---------------------------------------------------------------------------
__global__ void sumloss_kernel(const float* __restrict__ scores,
                               float* __restrict__ out, int nblk) {
    __shared__ float sh[8];
    __shared__ bool isLast;
    const int b = blockIdx.x;
    const int tid = threadIdx.x;
    float s = 0.f;
    const float* ps = &g_psum[b * MAX_BLK];
    for (int i = tid; i < nblk; i += 256)
        s += ps[i];
    #pragma unroll
    for (int off = 16; off; off >>= 1) s += __shfl_xor_sync(0xffffffffu, s, off);
    if ((tid & 31) == 0) sh[tid >> 5] = s;
    __syncthreads();
    if (tid == 0) {
        float S = 0.f;
        #pragma unroll
        for (int q = 0; q < 8; q++) S += sh[q];
        g_stot[b] = S;
        __threadfence();
        isLast = (atomicAdd(&g_ctr, 1u) == (unsigned)(B_ - 1));
    }
    __syncthreads();
    if (isLast && tid < 64) {
        float lv = scores[tid] * (logf(__ldcg(&g_stot[tid])) - g_tlogit[tid]);
        #pragma unroll
        for (int off = 16; off; off >>= 1) lv += __shfl_xor_sync(0xffffffffu, lv, off);
        if ((tid & 31) == 0) sh[tid >> 5] = lv;
    }
    __syncthreads();
    if (isLast && tid == 0) out[0] = sh[0] + sh[1];
}

// ---------------------------------------------------------------------------
extern "C" void kernel_launch(void* const* d_in, const int* in_sizes, int n_in,
                              void* d_out, int out_size) {
    const float* inputs   = (const float*)d_in[0];
    const float* scores   = (const float*)d_in[1];
    const float* features = (const float*)d_in[2];
    const int*   targets  = (const int*)d_in[3];
    int N = in_sizes[2] / D_;
    float* out = (float*)d_out;
    float* outF = out + 1;
    int nblk = (N + BM - 1) / BM;

    cudaFuncSetAttribute(main_kernel,
                         cudaFuncAttributeMaxDynamicSharedMemorySize, SMEM_BYTES);

    prep_kernel<<<B_, 32>>>(inputs, features, targets);
    main_kernel<<<nblk, 256, SMEM_BYTES>>>(features, scores, targets, outF, N);
    sumloss_kernel<<<B_, 256>>>(scores, out, nblk);
}